// round 1
// baseline (speedup 1.0000x reference)
#include <cuda_runtime.h>
#include <cstdint>
#include <math_constants.h>

#define BB   32
#define LQ   512
#define LK   2048
#define DD   768
#define NQC  16
#define QPC  (LQ/NQC)   // 32
#define NCH  16
#define KCH  (LK/NCH)   // 128
#define SUB  32
#define NSUB (KCH/SUB)  // 4
#define TPB  256

// scratch (device globals — no allocation allowed)
__device__ float g_sp  [BB*NQC*DD];
__device__ float g_ssum[BB*DD];
__device__ float g_qsum[BB*DD];
__device__ float g_w   [BB*DD];
__device__ float g_pm  [BB*NCH];
__device__ float g_pl  [BB*NCH];
__device__ float g_pacc[BB*NCH*DD];
__device__ float g_vin [BB*DD];

// ---------------- K1: partial row-sums of sentence_rep over q ----------------
__global__ void k_ssum_part(const float* __restrict__ sr) {
    int qc = blockIdx.x, b = blockIdx.y, d = threadIdx.x;
    const float* p = sr + ((size_t)b*LQ + (size_t)qc*QPC)*DD + d;
    float a = 0.f;
#pragma unroll
    for (int q = 0; q < QPC; q++) a += p[(size_t)q*DD];
    g_sp[(b*NQC + qc)*DD + d] = a;
}

// ---------------- K1b: reduce partials -> s_sum[b,d] ----------------
__global__ void k_ssum_reduce() {
    int b = blockIdx.x, d = threadIdx.x;
    float a = 0.f;
#pragma unroll
    for (int c = 0; c < NQC; c++) a += g_sp[(b*NQC + c)*DD + d];
    g_ssum[b*DD + d] = a;
}

// ---------------- K2: q_sum[b,e] = s_sum[b,:]·Wq[e,:] + 512*bq[e] ----------------
// grid = DD blocks (one per e), 128 threads, warp handles 8 b's
__global__ void k_qsum(const float* __restrict__ Wq, const float* __restrict__ bq) {
    int e = blockIdx.x;
    __shared__ float wrow[DD];
    for (int i = threadIdx.x; i < DD; i += 128) wrow[i] = Wq[(size_t)e*DD + i];
    __syncthreads();
    int warp = threadIdx.x >> 5, lane = threadIdx.x & 31;
    float be = 512.0f * bq[e];
    for (int b = warp; b < BB; b += 4) {
        const float* s = g_ssum + b*DD;
        float acc = 0.f;
#pragma unroll
        for (int i = 0; i < DD/32; i++) acc = fmaf(wrow[lane + 32*i], s[lane + 32*i], acc);
#pragma unroll
        for (int o = 16; o; o >>= 1) acc += __shfl_xor_sync(0xffffffffu, acc, o);
        if (lane == 0) g_qsum[b*DD + e] = acc + be;
    }
}

// ---------------- K3: w[b,d] = sum_e q_sum[b,e] * Wk[e,d] ----------------
// grid = (DD/128, BB/4), 128 threads; coalesced column reads of Wk
__global__ void k_w(const float* __restrict__ Wk) {
    int d  = blockIdx.x * 128 + threadIdx.x;
    int b0 = blockIdx.y * 4;
    __shared__ float qs[4*DD];
    for (int i = threadIdx.x; i < 4*DD; i += 128)
        qs[i] = g_qsum[(b0 + i/DD)*DD + (i % DD)];
    __syncthreads();
    float a0 = 0.f, a1 = 0.f, a2 = 0.f, a3 = 0.f;
#pragma unroll 8
    for (int e = 0; e < DD; e++) {
        float wk = Wk[(size_t)e*DD + d];
        a0 = fmaf(wk, qs[e],        a0);
        a1 = fmaf(wk, qs[DD   + e], a1);
        a2 = fmaf(wk, qs[2*DD + e], a2);
        a3 = fmaf(wk, qs[3*DD + e], a3);
    }
    g_w[(b0+0)*DD + d] = a0;
    g_w[(b0+1)*DD + d] = a1;
    g_w[(b0+2)*DD + d] = a2;
    g_w[(b0+3)*DD + d] = a3;
}

// ---------------- K4: fused scores + online softmax + weighted V-sum ----------------
// grid = (NCH, BB). One pass over comment_rep via cp.async double buffering.
// smem: 2 buffers of [SUB x DD] + w row + scores + p + (m,l,scale)
#define SMEM_FLOATS (2*SUB*DD + DD + 2*SUB + 4)

__global__ void __launch_bounds__(TPB) k_attn(const float* __restrict__ cr) {
    int b = blockIdx.y, ch = blockIdx.x;
    int tid = threadIdx.x, warp = tid >> 5, lane = tid & 31;
    extern __shared__ float sm[];
    float* buf0 = sm;
    float* buf1 = sm + SUB*DD;
    float* ws   = sm + 2*SUB*DD;
    float* ss   = ws + DD;
    float* ps   = ss + SUB;
    float* ml   = ps + SUB;   // [0]=m, [1]=l, [2]=scale

    const float* base = cr + ((size_t)b*LK + (size_t)ch*KCH)*DD;

    // issue load of subchunk 0
    {
        uint32_t sa = (uint32_t)__cvta_generic_to_shared(buf0);
        const float4* g = reinterpret_cast<const float4*>(base);
#pragma unroll
        for (int i = 0; i < (SUB*DD/4)/TPB; i++)
            asm volatile("cp.async.cg.shared.global [%0], [%1], 16;\n"
                :: "r"(sa + (uint32_t)((tid + i*TPB)*16)), "l"(g + tid + i*TPB));
        asm volatile("cp.async.commit_group;\n");
    }
    for (int i = tid; i < DD; i += TPB) ws[i] = g_w[b*DD + i];
    if (tid == 0) { ml[0] = -CUDART_INF_F; ml[1] = 0.0f; }

    float acc0 = 0.f, acc1 = 0.f, acc2 = 0.f;

    for (int sc = 0; sc < NSUB; sc++) {
        if (sc + 1 < NSUB) {
            float* nb = ((sc + 1) & 1) ? buf1 : buf0;
            uint32_t sa = (uint32_t)__cvta_generic_to_shared(nb);
            const float4* g = reinterpret_cast<const float4*>(base + (size_t)(sc+1)*SUB*DD);
#pragma unroll
            for (int i = 0; i < (SUB*DD/4)/TPB; i++)
                asm volatile("cp.async.cg.shared.global [%0], [%1], 16;\n"
                    :: "r"(sa + (uint32_t)((tid + i*TPB)*16)), "l"(g + tid + i*TPB));
            asm volatile("cp.async.commit_group;\n");
            asm volatile("cp.async.wait_group 1;\n");
        } else {
            asm volatile("cp.async.wait_group 0;\n");
        }
        __syncthreads();
        float* cb = (sc & 1) ? buf1 : buf0;

        // scores: 4 k per warp, warp-reduced dot with w
#pragma unroll
        for (int j = 0; j < SUB/8; j++) {
            int k = warp*(SUB/8) + j;
            const float* row = cb + k*DD;
            float s = 0.f;
#pragma unroll
            for (int i = 0; i < DD/32; i++)
                s = fmaf(row[lane + 32*i], ws[lane + 32*i], s);
#pragma unroll
            for (int o = 16; o; o >>= 1) s += __shfl_xor_sync(0xffffffffu, s, o);
            if (lane == 0) ss[k] = s;
        }
        __syncthreads();

        // online softmax update (warp 0)
        if (warp == 0) {
            float s = ss[lane];
            float m = s;
#pragma unroll
            for (int o = 16; o; o >>= 1) m = fmaxf(m, __shfl_xor_sync(0xffffffffu, m, o));
            float mold = ml[0];
            float mnew = fmaxf(mold, m);
            float p = __expf(s - mnew);
            ps[lane] = p;
            float sum = p;
#pragma unroll
            for (int o = 16; o; o >>= 1) sum += __shfl_xor_sync(0xffffffffu, sum, o);
            if (lane == 0) {
                float scale = __expf(mold - mnew);   // exp(-inf)=0 on first chunk
                ml[1] = ml[1]*scale + sum;
                ml[0] = mnew;
                ml[2] = scale;
            }
        }
        __syncthreads();

        float scale = ml[2];
        acc0 *= scale; acc1 *= scale; acc2 *= scale;
#pragma unroll
        for (int k = 0; k < SUB; k++) {
            float p = ps[k];
            acc0 = fmaf(p, cb[k*DD + tid],         acc0);
            acc1 = fmaf(p, cb[k*DD + tid + TPB],   acc1);
            acc2 = fmaf(p, cb[k*DD + tid + 2*TPB], acc2);
        }
        __syncthreads();   // buffer reuse safety before next issue
    }

    int cidx = b*NCH + ch;
    g_pacc[cidx*DD + tid]         = acc0;
    g_pacc[cidx*DD + tid + TPB]   = acc1;
    g_pacc[cidx*DD + tid + 2*TPB] = acc2;
    if (tid == 0) { g_pm[cidx] = ml[0]; g_pl[cidx] = ml[1]; }
}

// ---------------- K5a: combine chunk partials -> v_in[b,d] ----------------
__global__ void k_comb() {
    int b = blockIdx.x, tid = threadIdx.x;
    __shared__ float f[NCH];
    __shared__ float invL;
    if (tid == 0) {
        float M = -CUDART_INF_F;
        for (int c = 0; c < NCH; c++) M = fmaxf(M, g_pm[b*NCH + c]);
        float L = 0.f;
        for (int c = 0; c < NCH; c++) {
            float fc = __expf(g_pm[b*NCH + c] - M);
            f[c] = fc;
            L += g_pl[b*NCH + c] * fc;
        }
        invL = 1.0f / L;
    }
    __syncthreads();
#pragma unroll
    for (int j = 0; j < 3; j++) {
        int d = tid + j*TPB;
        float v = 0.f;
#pragma unroll
        for (int c = 0; c < NCH; c++)
            v = fmaf(g_pacc[(b*NCH + c)*DD + d], f[c], v);
        g_vin[b*DD + d] = v * invL;
    }
}

// ---------------- K5b: out[b,e] = v_in[b,:]·Wv[e,:] + bv[e] ----------------
__global__ void k_out(const float* __restrict__ Wv, const float* __restrict__ bv,
                      float* __restrict__ out) {
    int e = blockIdx.x;
    __shared__ float wrow[DD];
    for (int i = threadIdx.x; i < DD; i += 128) wrow[i] = Wv[(size_t)e*DD + i];
    __syncthreads();
    int warp = threadIdx.x >> 5, lane = threadIdx.x & 31;
    float bve = bv[e];
    for (int b = warp; b < BB; b += 4) {
        const float* v = g_vin + b*DD;
        float acc = 0.f;
#pragma unroll
        for (int i = 0; i < DD/32; i++) acc = fmaf(wrow[lane + 32*i], v[lane + 32*i], acc);
#pragma unroll
        for (int o = 16; o; o >>= 1) acc += __shfl_xor_sync(0xffffffffu, acc, o);
        if (lane == 0) out[b*DD + e] = acc + bve;
    }
}

extern "C" void kernel_launch(void* const* d_in, const int* in_sizes, int n_in,
                              void* d_out, int out_size) {
    const float* sr = (const float*)d_in[0];   // sentence_rep [32,512,768]
    const float* cr = (const float*)d_in[1];   // comment_rep  [32,2048,768]
    const float* Wq = (const float*)d_in[2];
    const float* bq = (const float*)d_in[3];
    const float* Wk = (const float*)d_in[4];
    // d_in[5] = bk — exactly cancels in softmax, unused
    const float* Wv = (const float*)d_in[6];
    const float* bv = (const float*)d_in[7];
    float* out = (float*)d_out;

    k_ssum_part<<<dim3(NQC, BB), DD>>>(sr);
    k_ssum_reduce<<<BB, DD>>>();
    k_qsum<<<DD, 128>>>(Wq, bq);
    k_w<<<dim3(DD/128, BB/4), 128>>>(Wk);

    size_t smem = SMEM_FLOATS * sizeof(float);
    cudaFuncSetAttribute(k_attn, cudaFuncAttributeMaxDynamicSharedMemorySize, (int)smem);
    k_attn<<<dim3(NCH, BB), TPB, smem>>>(cr);

    k_comb<<<BB, TPB>>>();
    k_out<<<DD, 128>>>(Wv, bv, out);
}

// round 2
// speedup vs baseline: 1.7207x; 1.7207x over previous
#include <cuda_runtime.h>
#include <cstdint>
#include <math_constants.h>

#define BB   32
#define LQ   512
#define LK   2048
#define DD   768
#define NQC  16
#define QPC  (LQ/NQC)   // 32
#define NCH  16
#define KCH  (LK/NCH)   // 128
#define SUB  16
#define NSUB (KCH/SUB)  // 8
#define TPB  256
#define ESPL 8
#define EPB  (DD/ESPL)  // 96

// scratch (device globals — no allocation allowed)
__device__ float g_sp  [BB*NQC*DD];
__device__ float g_ssum[BB*DD];
__device__ float g_qsum[BB*DD];
__device__ float g_wp  [ESPL*BB*DD];
__device__ float g_pm  [BB*NCH];
__device__ float g_pl  [BB*NCH];
__device__ float g_pacc[BB*NCH*DD];
__device__ float g_vin [BB*DD];

// ---------------- K1: partial row-sums of sentence_rep over q ----------------
__global__ void k_ssum_part(const float* __restrict__ sr) {
    int qc = blockIdx.x, b = blockIdx.y, d = threadIdx.x;
    const float* p = sr + ((size_t)b*LQ + (size_t)qc*QPC)*DD + d;
    float a = 0.f;
#pragma unroll
    for (int q = 0; q < QPC; q++) a += p[(size_t)q*DD];
    g_sp[(b*NQC + qc)*DD + d] = a;
}

// ---------------- K1b: reduce partials -> s_sum[b,d] ----------------
__global__ void k_ssum_reduce() {
    int b = blockIdx.x, d = threadIdx.x;
    float a = 0.f;
#pragma unroll
    for (int c = 0; c < NQC; c++) a += g_sp[(b*NQC + c)*DD + d];
    g_ssum[b*DD + d] = a;
}

// ---------------- K2: q_sum[b,e] = s_sum[b,:]·Wq[e,:] + 512*bq[e] ----------------
__global__ void k_qsum(const float* __restrict__ Wq, const float* __restrict__ bq) {
    int e = blockIdx.x;
    __shared__ float wrow[DD];
    for (int i = threadIdx.x; i < DD; i += 128) wrow[i] = Wq[(size_t)e*DD + i];
    __syncthreads();
    int warp = threadIdx.x >> 5, lane = threadIdx.x & 31;
    float be = 512.0f * bq[e];
    for (int b = warp; b < BB; b += 4) {
        const float* s = g_ssum + b*DD;
        float acc = 0.f;
#pragma unroll
        for (int i = 0; i < DD/32; i++) acc = fmaf(wrow[lane + 32*i], s[lane + 32*i], acc);
#pragma unroll
        for (int o = 16; o; o >>= 1) acc += __shfl_xor_sync(0xffffffffu, acc, o);
        if (lane == 0) g_qsum[b*DD + e] = acc + be;
    }
}

// ---------------- K3: w partials: g_wp[z,b,d] = sum_{e in split z} q_sum[b,e]*Wk[e,d] ----
// grid = (DD/128, BB/4, ESPL) = 384 blocks, 128 threads; coalesced column reads of Wk
__global__ void k_w(const float* __restrict__ Wk) {
    int d  = blockIdx.x * 128 + threadIdx.x;
    int b0 = blockIdx.y * 4;
    int e0 = blockIdx.z * EPB;
    __shared__ float qs[4*EPB];
    for (int i = threadIdx.x; i < 4*EPB; i += 128)
        qs[i] = g_qsum[(b0 + i/EPB)*DD + e0 + (i % EPB)];
    __syncthreads();
    float a0 = 0.f, a1 = 0.f, a2 = 0.f, a3 = 0.f;
#pragma unroll 8
    for (int e = 0; e < EPB; e++) {
        float wk = Wk[(size_t)(e0 + e)*DD + d];
        a0 = fmaf(wk, qs[e],         a0);
        a1 = fmaf(wk, qs[EPB   + e], a1);
        a2 = fmaf(wk, qs[2*EPB + e], a2);
        a3 = fmaf(wk, qs[3*EPB + e], a3);
    }
    int z = blockIdx.z;
    g_wp[(z*BB + b0+0)*DD + d] = a0;
    g_wp[(z*BB + b0+1)*DD + d] = a1;
    g_wp[(z*BB + b0+2)*DD + d] = a2;
    g_wp[(z*BB + b0+3)*DD + d] = a3;
}

// ---------------- K4: fused scores + online softmax + weighted V-sum ----------------
// grid = (NCH, BB). One pass over comment_rep via cp.async double buffering.
#define SMEM_FLOATS (2*SUB*DD + DD + 2*SUB + 4)

__global__ void __launch_bounds__(TPB) k_attn(const float* __restrict__ cr) {
    int b = blockIdx.y, ch = blockIdx.x;
    int tid = threadIdx.x, warp = tid >> 5, lane = tid & 31;
    extern __shared__ float sm[];
    float* buf0 = sm;
    float* buf1 = sm + SUB*DD;
    float* ws   = sm + 2*SUB*DD;
    float* ss   = ws + DD;
    float* ps   = ss + SUB;
    float* ml   = ps + SUB;   // [0]=m, [1]=l, [2]=scale

    const float* base = cr + ((size_t)b*LK + (size_t)ch*KCH)*DD;

    // issue load of subchunk 0
    {
        uint32_t sa = (uint32_t)__cvta_generic_to_shared(buf0);
        const float4* g = reinterpret_cast<const float4*>(base);
#pragma unroll
        for (int i = 0; i < (SUB*DD/4)/TPB; i++)
            asm volatile("cp.async.cg.shared.global [%0], [%1], 16;\n"
                :: "r"(sa + (uint32_t)((tid + i*TPB)*16)), "l"(g + tid + i*TPB));
        asm volatile("cp.async.commit_group;\n");
    }
    // ws = sum of e-split partials (L2-resident, cheap)
    for (int i = tid; i < DD; i += TPB) {
        float a = 0.f;
#pragma unroll
        for (int z = 0; z < ESPL; z++) a += g_wp[(z*BB + b)*DD + i];
        ws[i] = a;
    }
    if (tid == 0) { ml[0] = -CUDART_INF_F; ml[1] = 0.0f; }

    float acc0 = 0.f, acc1 = 0.f, acc2 = 0.f;

    for (int sc = 0; sc < NSUB; sc++) {
        if (sc + 1 < NSUB) {
            float* nb = ((sc + 1) & 1) ? buf1 : buf0;
            uint32_t sa = (uint32_t)__cvta_generic_to_shared(nb);
            const float4* g = reinterpret_cast<const float4*>(base + (size_t)(sc+1)*SUB*DD);
#pragma unroll
            for (int i = 0; i < (SUB*DD/4)/TPB; i++)
                asm volatile("cp.async.cg.shared.global [%0], [%1], 16;\n"
                    :: "r"(sa + (uint32_t)((tid + i*TPB)*16)), "l"(g + tid + i*TPB));
            asm volatile("cp.async.commit_group;\n");
            asm volatile("cp.async.wait_group 1;\n");
        } else {
            asm volatile("cp.async.wait_group 0;\n");
        }
        __syncthreads();
        float* cb = (sc & 1) ? buf1 : buf0;

        // scores: 2 k per warp, warp-reduced dot with w
#pragma unroll
        for (int j = 0; j < SUB/8; j++) {
            int k = warp*(SUB/8) + j;
            const float* row = cb + k*DD;
            float s = 0.f;
#pragma unroll
            for (int i = 0; i < DD/32; i++)
                s = fmaf(row[lane + 32*i], ws[lane + 32*i], s);
#pragma unroll
            for (int o = 16; o; o >>= 1) s += __shfl_xor_sync(0xffffffffu, s, o);
            if (lane == 0) ss[k] = s;
        }
        __syncthreads();

        // online softmax update (warp 0)
        if (warp == 0) {
            float s = (lane < SUB) ? ss[lane] : -CUDART_INF_F;
            float m = s;
#pragma unroll
            for (int o = 16; o; o >>= 1) m = fmaxf(m, __shfl_xor_sync(0xffffffffu, m, o));
            float mold = ml[0];
            float mnew = fmaxf(mold, m);
            float p = __expf(s - mnew);   // lanes >= SUB give exp(-inf)=0
            if (lane < SUB) ps[lane] = p;
            float sum = p;
#pragma unroll
            for (int o = 16; o; o >>= 1) sum += __shfl_xor_sync(0xffffffffu, sum, o);
            if (lane == 0) {
                float scale = __expf(mold - mnew);   // exp(-inf)=0 on first chunk
                ml[1] = ml[1]*scale + sum;
                ml[0] = mnew;
                ml[2] = scale;
            }
        }
        __syncthreads();

        float scale = ml[2];
        acc0 *= scale; acc1 *= scale; acc2 *= scale;
#pragma unroll
        for (int k = 0; k < SUB; k++) {
            float p = ps[k];
            acc0 = fmaf(p, cb[k*DD + tid],         acc0);
            acc1 = fmaf(p, cb[k*DD + tid + TPB],   acc1);
            acc2 = fmaf(p, cb[k*DD + tid + 2*TPB], acc2);
        }
        __syncthreads();   // buffer reuse safety before next issue
    }

    int cidx = b*NCH + ch;
    g_pacc[cidx*DD + tid]         = acc0;
    g_pacc[cidx*DD + tid + TPB]   = acc1;
    g_pacc[cidx*DD + tid + 2*TPB] = acc2;
    if (tid == 0) { g_pm[cidx] = ml[0]; g_pl[cidx] = ml[1]; }
}

// ---------------- K5a: combine chunk partials -> v_in[b,d] ----------------
__global__ void k_comb() {
    int b = blockIdx.x, tid = threadIdx.x;
    __shared__ float f[NCH];
    __shared__ float invL;
    if (tid == 0) {
        float M = -CUDART_INF_F;
        for (int c = 0; c < NCH; c++) M = fmaxf(M, g_pm[b*NCH + c]);
        float L = 0.f;
        for (int c = 0; c < NCH; c++) {
            float fc = __expf(g_pm[b*NCH + c] - M);
            f[c] = fc;
            L += g_pl[b*NCH + c] * fc;
        }
        invL = 1.0f / L;
    }
    __syncthreads();
#pragma unroll
    for (int j = 0; j < 3; j++) {
        int d = tid + j*TPB;
        float v = 0.f;
#pragma unroll
        for (int c = 0; c < NCH; c++)
            v = fmaf(g_pacc[(b*NCH + c)*DD + d], f[c], v);
        g_vin[b*DD + d] = v * invL;
    }
}

// ---------------- K5b: out[b,e] = v_in[b,:]·Wv[e,:] + bv[e] ----------------
__global__ void k_out(const float* __restrict__ Wv, const float* __restrict__ bv,
                      float* __restrict__ out) {
    int e = blockIdx.x;
    __shared__ float wrow[DD];
    for (int i = threadIdx.x; i < DD; i += 128) wrow[i] = Wv[(size_t)e*DD + i];
    __syncthreads();
    int warp = threadIdx.x >> 5, lane = threadIdx.x & 31;
    float bve = bv[e];
    for (int b = warp; b < BB; b += 4) {
        const float* v = g_vin + b*DD;
        float acc = 0.f;
#pragma unroll
        for (int i = 0; i < DD/32; i++) acc = fmaf(wrow[lane + 32*i], v[lane + 32*i], acc);
#pragma unroll
        for (int o = 16; o; o >>= 1) acc += __shfl_xor_sync(0xffffffffu, acc, o);
        if (lane == 0) out[b*DD + e] = acc + bve;
    }
}

extern "C" void kernel_launch(void* const* d_in, const int* in_sizes, int n_in,
                              void* d_out, int out_size) {
    const float* sr = (const float*)d_in[0];   // sentence_rep [32,512,768]
    const float* cr = (const float*)d_in[1];   // comment_rep  [32,2048,768]
    const float* Wq = (const float*)d_in[2];
    const float* bq = (const float*)d_in[3];
    const float* Wk = (const float*)d_in[4];
    // d_in[5] = bk — exactly cancels in softmax, unused
    const float* Wv = (const float*)d_in[6];
    const float* bv = (const float*)d_in[7];
    float* out = (float*)d_out;

    k_ssum_part<<<dim3(NQC, BB), DD>>>(sr);
    k_ssum_reduce<<<BB, DD>>>();
    k_qsum<<<DD, 128>>>(Wq, bq);
    k_w<<<dim3(DD/128, BB/4, ESPL), 128>>>(Wk);

    size_t smem = SMEM_FLOATS * sizeof(float);
    cudaFuncSetAttribute(k_attn, cudaFuncAttributeMaxDynamicSharedMemorySize, (int)smem);
    k_attn<<<dim3(NCH, BB), TPB, smem>>>(cr);

    k_comb<<<BB, TPB>>>();
    k_out<<<DD, 128>>>(Wv, bv, out);
}

// round 3
// speedup vs baseline: 2.4497x; 1.4237x over previous
#include <cuda_runtime.h>
#include <cstdint>
#include <math_constants.h>

#define BB   32
#define LQ   512
#define LK   2048
#define DD   768
#define NQC  16
#define QPC  (LQ/NQC)   // 32
#define NCH  8
#define KCH  (LK/NCH)   // 256
#define SUB  16
#define NSUB (KCH/SUB)  // 16
#define TPB  256
#define ESPL 16
#define EPB  (DD/ESPL)  // 48

// scratch (device globals — no allocation allowed)
__device__ float g_sp  [BB*NQC*DD];
__device__ float g_ssum[BB*DD];
__device__ float g_qsum[BB*DD];
__device__ float g_wp  [ESPL*BB*DD];
__device__ float g_pm  [BB*NCH];
__device__ float g_pl  [BB*NCH];
__device__ float g_pacc[BB*NCH*DD];
__device__ float g_vin [BB*DD];

// ---------------- K1: partial row-sums of sentence_rep over q ----------------
__global__ void k_ssum_part(const float* __restrict__ sr) {
    int qc = blockIdx.x, b = blockIdx.y, d = threadIdx.x;
    const float* p = sr + ((size_t)b*LQ + (size_t)qc*QPC)*DD + d;
    float a0 = 0.f, a1 = 0.f;
#pragma unroll
    for (int q = 0; q < QPC; q += 2) {
        a0 += p[(size_t)q*DD];
        a1 += p[(size_t)(q+1)*DD];
    }
    g_sp[(b*NQC + qc)*DD + d] = a0 + a1;
}

// ---------------- K1b: reduce partials -> s_sum[b,d] ----------------
__global__ void k_ssum_reduce() {
    int b = blockIdx.x, d = threadIdx.x;
    float a = 0.f;
#pragma unroll
    for (int c = 0; c < NQC; c++) a += g_sp[(b*NQC + c)*DD + d];
    g_ssum[b*DD + d] = a;
}

// ---------------- K2: q_sum[b,e] = s_sum[b,:]·Wq[e,:] + 512*bq[e] ----------------
__global__ void k_qsum(const float* __restrict__ Wq, const float* __restrict__ bq) {
    int e = blockIdx.x;
    __shared__ float wrow[DD];
    for (int i = threadIdx.x; i < DD/4; i += 128)
        reinterpret_cast<float4*>(wrow)[i] =
            reinterpret_cast<const float4*>(Wq + (size_t)e*DD)[i];
    __syncthreads();
    int warp = threadIdx.x >> 5, lane = threadIdx.x & 31;
    float be = 512.0f * bq[e];
    const float4* w4 = reinterpret_cast<const float4*>(wrow);
    for (int b = warp; b < BB; b += 4) {
        const float4* s4 = reinterpret_cast<const float4*>(g_ssum + b*DD);
        float acc = 0.f;
#pragma unroll
        for (int i = 0; i < DD/128; i++) {
            float4 w = w4[lane + 32*i], s = s4[lane + 32*i];
            acc = fmaf(w.x, s.x, acc); acc = fmaf(w.y, s.y, acc);
            acc = fmaf(w.z, s.z, acc); acc = fmaf(w.w, s.w, acc);
        }
#pragma unroll
        for (int o = 16; o; o >>= 1) acc += __shfl_xor_sync(0xffffffffu, acc, o);
        if (lane == 0) g_qsum[b*DD + e] = acc + be;
    }
}

// ---------------- K3: w partials: g_wp[z,b,d] = sum_{e in split z} q_sum[b,e]*Wk[e,d] ----
// grid = (DD/128, BB/2, ESPL) = 1536 blocks, 128 threads
__global__ void k_w(const float* __restrict__ Wk) {
    int d  = blockIdx.x * 128 + threadIdx.x;
    int b0 = blockIdx.y * 2;
    int e0 = blockIdx.z * EPB;
    __shared__ float qs[2*EPB];
    if (threadIdx.x < 2*EPB)
        qs[threadIdx.x] = g_qsum[(b0 + threadIdx.x/EPB)*DD + e0 + (threadIdx.x % EPB)];
    __syncthreads();
    float a0 = 0.f, a1 = 0.f;
#pragma unroll 8
    for (int e = 0; e < EPB; e++) {
        float wk = Wk[(size_t)(e0 + e)*DD + d];
        a0 = fmaf(wk, qs[e],       a0);
        a1 = fmaf(wk, qs[EPB + e], a1);
    }
    int z = blockIdx.z;
    g_wp[(z*BB + b0+0)*DD + d] = a0;
    g_wp[(z*BB + b0+1)*DD + d] = a1;
}

// ---------------- K4: fused scores + online softmax + weighted V-sum ----------------
// grid = (NCH, BB) = 256 blocks, single wave at 2 blocks/SM.
#define SMEM_FLOATS (2*SUB*DD + DD + 2*SUB + 4)

__global__ void __launch_bounds__(TPB) k_attn(const float* __restrict__ cr) {
    int b = blockIdx.y, ch = blockIdx.x;
    int tid = threadIdx.x, warp = tid >> 5, lane = tid & 31;
    extern __shared__ float sm[];
    float* buf0 = sm;
    float* buf1 = sm + SUB*DD;
    float* ws   = sm + 2*SUB*DD;
    float* ss   = ws + DD;
    float* ps   = ss + SUB;
    float* ml   = ps + SUB;   // [0]=m, [1]=l, [2]=scale

    const float* base = cr + ((size_t)b*LK + (size_t)ch*KCH)*DD;

    // issue load of subchunk 0
    {
        uint32_t sa = (uint32_t)__cvta_generic_to_shared(buf0);
        const float4* g = reinterpret_cast<const float4*>(base);
#pragma unroll
        for (int i = 0; i < (SUB*DD/4)/TPB; i++)
            asm volatile("cp.async.cg.shared.global [%0], [%1], 16;\n"
                :: "r"(sa + (uint32_t)((tid + i*TPB)*16)), "l"(g + tid + i*TPB));
        asm volatile("cp.async.commit_group;\n");
    }
    // ws = sum of e-split partials (L2-resident)
    for (int i = tid; i < DD; i += TPB) {
        float a = 0.f;
#pragma unroll
        for (int z = 0; z < ESPL; z++) a += g_wp[(z*BB + b)*DD + i];
        ws[i] = a;
    }
    if (tid == 0) { ml[0] = -CUDART_INF_F; ml[1] = 0.0f; }

    float4 acc = make_float4(0.f, 0.f, 0.f, 0.f);
    const float4* ws4 = reinterpret_cast<const float4*>(ws);

    for (int sc = 0; sc < NSUB; sc++) {
        if (sc + 1 < NSUB) {
            float* nb = ((sc + 1) & 1) ? buf1 : buf0;
            uint32_t sa = (uint32_t)__cvta_generic_to_shared(nb);
            const float4* g = reinterpret_cast<const float4*>(base + (size_t)(sc+1)*SUB*DD);
#pragma unroll
            for (int i = 0; i < (SUB*DD/4)/TPB; i++)
                asm volatile("cp.async.cg.shared.global [%0], [%1], 16;\n"
                    :: "r"(sa + (uint32_t)((tid + i*TPB)*16)), "l"(g + tid + i*TPB));
            asm volatile("cp.async.commit_group;\n");
            asm volatile("cp.async.wait_group 1;\n");
        } else {
            asm volatile("cp.async.wait_group 0;\n");
        }
        __syncthreads();
        float* cb = (sc & 1) ? buf1 : buf0;
        const float4* cb4 = reinterpret_cast<const float4*>(cb);

        // scores: 2 k per warp, vectorized warp-reduced dot with w
#pragma unroll
        for (int j = 0; j < SUB/8; j++) {
            int k = warp*(SUB/8) + j;
            const float4* row4 = reinterpret_cast<const float4*>(cb + k*DD);
            float s = 0.f;
#pragma unroll
            for (int i = 0; i < DD/128; i++) {
                float4 a = row4[lane + 32*i], w = ws4[lane + 32*i];
                s = fmaf(a.x, w.x, s); s = fmaf(a.y, w.y, s);
                s = fmaf(a.z, w.z, s); s = fmaf(a.w, w.w, s);
            }
#pragma unroll
            for (int o = 16; o; o >>= 1) s += __shfl_xor_sync(0xffffffffu, s, o);
            if (lane == 0) ss[k] = s;
        }
        __syncthreads();

        // online softmax update (warp 0)
        if (warp == 0) {
            float s = (lane < SUB) ? ss[lane] : -CUDART_INF_F;
            float m = s;
#pragma unroll
            for (int o = 16; o; o >>= 1) m = fmaxf(m, __shfl_xor_sync(0xffffffffu, m, o));
            float mold = ml[0];
            float mnew = fmaxf(mold, m);
            float p = __expf(s - mnew);
            if (lane < SUB) ps[lane] = p;
            float sum = p;
#pragma unroll
            for (int o = 16; o; o >>= 1) sum += __shfl_xor_sync(0xffffffffu, sum, o);
            if (lane == 0) {
                float scale = __expf(mold - mnew);   // exp(-inf)=0 on first chunk
                ml[1] = ml[1]*scale + sum;
                ml[0] = mnew;
                ml[2] = scale;
            }
        }
        __syncthreads();

        // weighted V accumulation: threads 0..191, float4 per thread
        if (tid < DD/4) {
            float scale = ml[2];
            acc.x *= scale; acc.y *= scale; acc.z *= scale; acc.w *= scale;
#pragma unroll
            for (int k = 0; k < SUB; k++) {
                float p = ps[k];
                float4 v = cb4[k*(DD/4) + tid];
                acc.x = fmaf(p, v.x, acc.x);
                acc.y = fmaf(p, v.y, acc.y);
                acc.z = fmaf(p, v.z, acc.z);
                acc.w = fmaf(p, v.w, acc.w);
            }
        }
        __syncthreads();   // buffer reuse safety before next issue
    }

    int cidx = b*NCH + ch;
    if (tid < DD/4)
        reinterpret_cast<float4*>(g_pacc)[cidx*(DD/4) + tid] = acc;
    if (tid == 0) { g_pm[cidx] = ml[0]; g_pl[cidx] = ml[1]; }
}

// ---------------- K5a: combine chunk partials -> v_in[b,d] ----------------
__global__ void k_comb() {
    int b = blockIdx.x, tid = threadIdx.x;   // 192 threads
    __shared__ float f[NCH];
    __shared__ float invL;
    if (tid == 0) {
        float M = -CUDART_INF_F;
        for (int c = 0; c < NCH; c++) M = fmaxf(M, g_pm[b*NCH + c]);
        float L = 0.f;
        for (int c = 0; c < NCH; c++) {
            float fc = __expf(g_pm[b*NCH + c] - M);
            f[c] = fc;
            L += g_pl[b*NCH + c] * fc;
        }
        invL = 1.0f / L;
    }
    __syncthreads();
    float4 v = make_float4(0.f, 0.f, 0.f, 0.f);
#pragma unroll
    for (int c = 0; c < NCH; c++) {
        float fc = f[c];
        float4 a = reinterpret_cast<const float4*>(g_pacc)[(b*NCH + c)*(DD/4) + tid];
        v.x = fmaf(a.x, fc, v.x); v.y = fmaf(a.y, fc, v.y);
        v.z = fmaf(a.z, fc, v.z); v.w = fmaf(a.w, fc, v.w);
    }
    v.x *= invL; v.y *= invL; v.z *= invL; v.w *= invL;
    reinterpret_cast<float4*>(g_vin)[b*(DD/4) + tid] = v;
}

// ---------------- K5b: out[b,e] = v_in[b,:]·Wv[e,:] + bv[e] ----------------
__global__ void k_out(const float* __restrict__ Wv, const float* __restrict__ bv,
                      float* __restrict__ out) {
    int e = blockIdx.x;
    __shared__ float wrow[DD];
    for (int i = threadIdx.x; i < DD/4; i += 128)
        reinterpret_cast<float4*>(wrow)[i] =
            reinterpret_cast<const float4*>(Wv + (size_t)e*DD)[i];
    __syncthreads();
    int warp = threadIdx.x >> 5, lane = threadIdx.x & 31;
    float bve = bv[e];
    const float4* w4 = reinterpret_cast<const float4*>(wrow);
    for (int b = warp; b < BB; b += 4) {
        const float4* v4 = reinterpret_cast<const float4*>(g_vin + b*DD);
        float acc = 0.f;
#pragma unroll
        for (int i = 0; i < DD/128; i++) {
            float4 w = w4[lane + 32*i], v = v4[lane + 32*i];
            acc = fmaf(w.x, v.x, acc); acc = fmaf(w.y, v.y, acc);
            acc = fmaf(w.z, v.z, acc); acc = fmaf(w.w, v.w, acc);
        }
#pragma unroll
        for (int o = 16; o; o >>= 1) acc += __shfl_xor_sync(0xffffffffu, acc, o);
        if (lane == 0) out[b*DD + e] = acc + bve;
    }
}

extern "C" void kernel_launch(void* const* d_in, const int* in_sizes, int n_in,
                              void* d_out, int out_size) {
    const float* sr = (const float*)d_in[0];   // sentence_rep [32,512,768]
    const float* cr = (const float*)d_in[1];   // comment_rep  [32,2048,768]
    const float* Wq = (const float*)d_in[2];
    const float* bq = (const float*)d_in[3];
    const float* Wk = (const float*)d_in[4];
    // d_in[5] = bk — exactly cancels in softmax, unused
    const float* Wv = (const float*)d_in[6];
    const float* bv = (const float*)d_in[7];
    float* out = (float*)d_out;

    k_ssum_part<<<dim3(NQC, BB), DD>>>(sr);
    k_ssum_reduce<<<BB, DD>>>();
    k_qsum<<<DD, 128>>>(Wq, bq);
    k_w<<<dim3(DD/128, BB/2, ESPL), 128>>>(Wk);

    size_t smem = SMEM_FLOATS * sizeof(float);
    cudaFuncSetAttribute(k_attn, cudaFuncAttributeMaxDynamicSharedMemorySize, (int)smem);
    k_attn<<<dim3(NCH, BB), TPB, smem>>>(cr);

    k_comb<<<BB, DD/4>>>();
    k_out<<<DD, 128>>>(Wv, bv, out);
}